// round 1
// baseline (speedup 1.0000x reference)
#include <cuda_runtime.h>

// Problem constants
#define S_LEN  2048
#define DIMV   1024
#define NHEAD  16
#define HD     64
#define BATCH  2
#define M_ROWS (BATCH * S_LEN)     // 4096
#define KDIM   1024
#define NDIM   1024
#define BHEADS (BATCH * NHEAD)     // 32
#define CHUNK  128
#define NCHUNK (S_LEN / CHUNK)     // 16

// ---------------------------------------------------------------------------
// Scratch (static device globals: allocation-free per harness rules)
// ---------------------------------------------------------------------------
__device__ float g_q[M_ROWS * DIMV];
__device__ float g_k[M_ROWS * DIMV];
__device__ float g_v[M_ROWS * DIMV];
__device__ float g_att[M_ROWS * DIMV];
__device__ float g_ckv[BHEADS * NCHUNK * HD * HD];  // per-chunk sum k v^T
__device__ float g_ck1[BHEADS * NCHUNK * HD];       // per-chunk sum k
__device__ float g_pkv[BHEADS * NCHUNK * HD * HD];  // exclusive prefixes
__device__ float g_pk1[BHEADS * NCHUNK * HD];

#define SMS 132  // padded shared stride (multiple of 4 for float4 alignment)

// ---------------------------------------------------------------------------
// NT SGEMM: C[m,n] = sum_k A[m,k] * W[n,k] + bias[n], optional exp epilogue.
// Block tile 128x128, BK=16, 256 threads, 8x8 microtile per thread.
// ---------------------------------------------------------------------------
__device__ __forceinline__ void gemm_nt_body(
    const float* __restrict__ A, const float* __restrict__ W,
    const float* __restrict__ bias, float* __restrict__ Co, bool doExp)
{
    __shared__ float As[16 * SMS];
    __shared__ float Bs[16 * SMS];
    const int tid  = threadIdx.x;
    const int lrow = tid >> 2;   // 0..63 : 4 lanes per row -> 64B coalesced
    const int lkv  = tid & 3;    // 0..3
    const int tx   = tid & 15;
    const int ty   = tid >> 4;
    const int m0 = blockIdx.y * 128;
    const int n0 = blockIdx.x * 128;

    const float* Ap = A + (size_t)(m0 + lrow) * KDIM + lkv * 4;
    const float* Wp = W + (size_t)(n0 + lrow) * KDIM + lkv * 4;

    float acc[8][8];
#pragma unroll
    for (int i = 0; i < 8; i++)
#pragma unroll
        for (int j = 0; j < 8; j++) acc[i][j] = 0.f;

    for (int k0 = 0; k0 < KDIM; k0 += 16) {
        float4 a0 = *(const float4*)(Ap + k0);
        float4 a1 = *(const float4*)(Ap + (size_t)64 * KDIM + k0);
        float4 w0 = *(const float4*)(Wp + k0);
        float4 w1 = *(const float4*)(Wp + (size_t)64 * KDIM + k0);
        __syncthreads();
        As[(lkv * 4 + 0) * SMS + lrow]      = a0.x;
        As[(lkv * 4 + 1) * SMS + lrow]      = a0.y;
        As[(lkv * 4 + 2) * SMS + lrow]      = a0.z;
        As[(lkv * 4 + 3) * SMS + lrow]      = a0.w;
        As[(lkv * 4 + 0) * SMS + lrow + 64] = a1.x;
        As[(lkv * 4 + 1) * SMS + lrow + 64] = a1.y;
        As[(lkv * 4 + 2) * SMS + lrow + 64] = a1.z;
        As[(lkv * 4 + 3) * SMS + lrow + 64] = a1.w;
        Bs[(lkv * 4 + 0) * SMS + lrow]      = w0.x;
        Bs[(lkv * 4 + 1) * SMS + lrow]      = w0.y;
        Bs[(lkv * 4 + 2) * SMS + lrow]      = w0.z;
        Bs[(lkv * 4 + 3) * SMS + lrow]      = w0.w;
        Bs[(lkv * 4 + 0) * SMS + lrow + 64] = w1.x;
        Bs[(lkv * 4 + 1) * SMS + lrow + 64] = w1.y;
        Bs[(lkv * 4 + 2) * SMS + lrow + 64] = w1.z;
        Bs[(lkv * 4 + 3) * SMS + lrow + 64] = w1.w;
        __syncthreads();
#pragma unroll
        for (int kk = 0; kk < 16; kk++) {
            float af[8], bf[8];
            *(float4*)(af)     = *(const float4*)&As[kk * SMS + ty * 8];
            *(float4*)(af + 4) = *(const float4*)&As[kk * SMS + ty * 8 + 4];
            *(float4*)(bf)     = *(const float4*)&Bs[kk * SMS + tx * 8];
            *(float4*)(bf + 4) = *(const float4*)&Bs[kk * SMS + tx * 8 + 4];
#pragma unroll
            for (int i = 0; i < 8; i++)
#pragma unroll
                for (int j = 0; j < 8; j++)
                    acc[i][j] = fmaf(af[i], bf[j], acc[i][j]);
        }
    }

    float bv[8];
#pragma unroll
    for (int j = 0; j < 8; j++) bv[j] = bias[n0 + tx * 8 + j];
#pragma unroll
    for (int i = 0; i < 8; i++) {
        const int row = m0 + ty * 8 + i;
        float o[8];
#pragma unroll
        for (int j = 0; j < 8; j++) {
            float v = acc[i][j] + bv[j];
            o[j] = doExp ? expf(v) : v;
        }
        *(float4*)&Co[(size_t)row * NDIM + n0 + tx * 8]     = *(float4*)o;
        *(float4*)&Co[(size_t)row * NDIM + n0 + tx * 8 + 4] = *(float4*)(o + 4);
    }
}

__global__ void __launch_bounds__(256) qkv_gemm_kernel(
    const float* __restrict__ x,
    const float* __restrict__ Wq, const float* __restrict__ bq,
    const float* __restrict__ Wk, const float* __restrict__ bk,
    const float* __restrict__ Wv, const float* __restrict__ bv)
{
    const int z = blockIdx.z;
    const float* W    = (z == 0) ? Wq : ((z == 1) ? Wk : Wv);
    const float* bias = (z == 0) ? bq : ((z == 1) ? bk : bv);
    float* out        = (z == 0) ? g_q : ((z == 1) ? g_k : g_v);
    gemm_nt_body(x, W, bias, out, z < 2);  // q,k get exp; v does not
}

__global__ void __launch_bounds__(256) out_gemm_kernel(
    const float* __restrict__ Wo, const float* __restrict__ bo,
    float* __restrict__ out)
{
    gemm_nt_body(g_att, Wo, bo, out, false);
}

// ---------------------------------------------------------------------------
// Chunk stats: per (head, chunk) compute sum_t k_t v_t^T (64x64) and sum_t k_t
// ---------------------------------------------------------------------------
__global__ void __launch_bounds__(256) chunk_stats_kernel()
{
    extern __shared__ __align__(16) float sm[];
    float* Ks = sm;                    // [128][64]
    float* Vs = sm + CHUNK * HD;       // [128][64]
    const int bh = blockIdx.y, c = blockIdx.x;
    const int b = bh >> 4, h = bh & 15;
    const int tid = threadIdx.x;
    const size_t base = ((size_t)(b * S_LEN + c * CHUNK)) * DIMV + h * HD;

#pragma unroll
    for (int it = 0; it < 8; it++) {
        const int idx = tid + it * 256;     // 0..2047
        const int t = idx >> 4, dv = idx & 15;
        *(float4*)&Ks[t * HD + dv * 4] =
            *(const float4*)(g_k + base + (size_t)t * DIMV + dv * 4);
        *(float4*)&Vs[t * HD + dv * 4] =
            *(const float4*)(g_v + base + (size_t)t * DIMV + dv * 4);
    }
    __syncthreads();

    const int tx = tid & 15, ty = tid >> 4;
    float acc[4][4];
#pragma unroll
    for (int i = 0; i < 4; i++)
#pragma unroll
        for (int j = 0; j < 4; j++) acc[i][j] = 0.f;

#pragma unroll 4
    for (int t = 0; t < CHUNK; t++) {
        float kf[4], vf[4];
        *(float4*)kf = *(const float4*)&Ks[t * HD + ty * 4];
        *(float4*)vf = *(const float4*)&Vs[t * HD + tx * 4];
#pragma unroll
        for (int i = 0; i < 4; i++)
#pragma unroll
            for (int j = 0; j < 4; j++)
                acc[i][j] = fmaf(kf[i], vf[j], acc[i][j]);
    }

    float* okv = g_ckv + ((size_t)bh * NCHUNK + c) * HD * HD;
#pragma unroll
    for (int i = 0; i < 4; i++)
        *(float4*)&okv[(ty * 4 + i) * HD + tx * 4] = *(float4*)acc[i];

    if (tid < HD) {
        float s = 0.f;
#pragma unroll 8
        for (int t = 0; t < CHUNK; t++) s += Ks[t * HD + tid];
        g_ck1[((size_t)bh * NCHUNK + c) * HD + tid] = s;
    }
}

// ---------------------------------------------------------------------------
// Exclusive prefix over the 16 chunk states per head
// ---------------------------------------------------------------------------
__global__ void __launch_bounds__(256) prefix_kernel()
{
    const int bh = blockIdx.x, tid = threadIdx.x;
    for (int e = tid; e < HD * HD; e += 256) {
        float run = 0.f;
#pragma unroll
        for (int c = 0; c < NCHUNK; c++) {
            const size_t off = ((size_t)bh * NCHUNK + c) * HD * HD + e;
            g_pkv[off] = run;
            run += g_ckv[off];
        }
    }
    if (tid < HD) {
        float run = 0.f;
#pragma unroll
        for (int c = 0; c < NCHUNK; c++) {
            const size_t off = ((size_t)bh * NCHUNK + c) * HD + tid;
            g_pk1[off] = run;
            run += g_ck1[off];
        }
    }
}

// ---------------------------------------------------------------------------
// Chunk output: out_t = (q_t @ KVprev + sum_{t'<=t} (q_t.k_t') v_t') / den_t
// A = Q K^T (causal-masked) staged in shared. 256 threads, ~181KB dyn smem.
// ---------------------------------------------------------------------------
__global__ void __launch_bounds__(256) chunk_out_kernel()
{
    extern __shared__ __align__(16) float sm[];
    float* QsT  = sm;                       // [64][132] transposed
    float* KsT  = QsT + HD * SMS;           // [64][132] transposed
    float* Vs   = KsT + HD * SMS;           // [128][64]
    float* Sp   = Vs + CHUNK * HD;          // [64][64] kv prefix
    float* Am   = Sp + HD * HD;             // [128][132] masked A
    float* k1p  = Am + CHUNK * SMS;         // [64]
    float* dens = k1p + HD;                 // [128]

    const int bh = blockIdx.y, c = blockIdx.x;
    const int b = bh >> 4, h = bh & 15;
    const int tid = threadIdx.x;
    const size_t base = ((size_t)(b * S_LEN + c * CHUNK)) * DIMV + h * HD;

    // loads (Q,K transposed for conflict-free microtile reads)
#pragma unroll
    for (int it = 0; it < 8; it++) {
        const int idx = tid + it * 256;
        const int t = idx >> 4, dv = idx & 15;
        float4 q4 = *(const float4*)(g_q + base + (size_t)t * DIMV + dv * 4);
        float4 k4 = *(const float4*)(g_k + base + (size_t)t * DIMV + dv * 4);
        float4 v4 = *(const float4*)(g_v + base + (size_t)t * DIMV + dv * 4);
        QsT[(dv * 4 + 0) * SMS + t] = q4.x;
        QsT[(dv * 4 + 1) * SMS + t] = q4.y;
        QsT[(dv * 4 + 2) * SMS + t] = q4.z;
        QsT[(dv * 4 + 3) * SMS + t] = q4.w;
        KsT[(dv * 4 + 0) * SMS + t] = k4.x;
        KsT[(dv * 4 + 1) * SMS + t] = k4.y;
        KsT[(dv * 4 + 2) * SMS + t] = k4.z;
        KsT[(dv * 4 + 3) * SMS + t] = k4.w;
        *(float4*)&Vs[t * HD + dv * 4] = v4;
    }
    {
        const float* spg = g_pkv + ((size_t)bh * NCHUNK + c) * HD * HD;
#pragma unroll
        for (int it = 0; it < 4; it++) {
            const int idx = (tid + it * 256) * 4;
            *(float4*)&Sp[idx] = *(const float4*)&spg[idx];
        }
        if (tid < HD) k1p[tid] = g_pk1[((size_t)bh * NCHUNK + c) * HD + tid];
    }
    __syncthreads();

    const int tx = tid & 15, ty = tid >> 4;

    // phase 2: A = Q K^T, causal mask applied on store
    {
        float acc[8][8];
#pragma unroll
        for (int i = 0; i < 8; i++)
#pragma unroll
            for (int j = 0; j < 8; j++) acc[i][j] = 0.f;
#pragma unroll 4
        for (int kk = 0; kk < HD; kk++) {
            float qf[8], kf[8];
            *(float4*)(qf)     = *(const float4*)&QsT[kk * SMS + ty * 8];
            *(float4*)(qf + 4) = *(const float4*)&QsT[kk * SMS + ty * 8 + 4];
            *(float4*)(kf)     = *(const float4*)&KsT[kk * SMS + tx * 8];
            *(float4*)(kf + 4) = *(const float4*)&KsT[kk * SMS + tx * 8 + 4];
#pragma unroll
            for (int i = 0; i < 8; i++)
#pragma unroll
                for (int j = 0; j < 8; j++)
                    acc[i][j] = fmaf(qf[i], kf[j], acc[i][j]);
        }
#pragma unroll
        for (int i = 0; i < 8; i++) {
            const int t = ty * 8 + i;
            float o[8];
#pragma unroll
            for (int j = 0; j < 8; j++) {
                const int tp = tx * 8 + j;
                o[j] = (tp <= t) ? acc[i][j] : 0.f;
            }
            *(float4*)&Am[t * SMS + tx * 8]     = *(float4*)o;
            *(float4*)&Am[t * SMS + tx * 8 + 4] = *(float4*)(o + 4);
        }
    }
    __syncthreads();

    // denominator per row
    if (tid < CHUNK) {
        const int t = tid;
        float s = 0.f;
#pragma unroll 8
        for (int d = 0; d < HD; d++) s = fmaf(QsT[d * SMS + t], k1p[d], s);
        for (int tp = 0; tp <= t; tp++) s += Am[t * SMS + tp];
        dens[t] = s;
    }
    __syncthreads();

    // phase 3: out = Am @ V + Q @ Sp, each thread 8(t) x 4(d)
    {
        float acc[8][4];
#pragma unroll
        for (int i = 0; i < 8; i++)
#pragma unroll
            for (int j = 0; j < 4; j++) acc[i][j] = 0.f;
#pragma unroll 4
        for (int tp = 0; tp < CHUNK; tp++) {
            float vf[4];
            *(float4*)vf = *(const float4*)&Vs[tp * HD + tx * 4];
#pragma unroll
            for (int i = 0; i < 8; i++) {
                const float a = Am[(ty * 8 + i) * SMS + tp];
#pragma unroll
                for (int j = 0; j < 4; j++) acc[i][j] = fmaf(a, vf[j], acc[i][j]);
            }
        }
#pragma unroll 4
        for (int d1 = 0; d1 < HD; d1++) {
            float vf[4];
            *(float4*)vf = *(const float4*)&Sp[d1 * HD + tx * 4];
#pragma unroll
            for (int i = 0; i < 8; i++) {
                const float a = QsT[d1 * SMS + ty * 8 + i];
#pragma unroll
                for (int j = 0; j < 4; j++) acc[i][j] = fmaf(a, vf[j], acc[i][j]);
            }
        }
#pragma unroll
        for (int i = 0; i < 8; i++) {
            const int t = ty * 8 + i;
            const float inv = 1.0f / dens[t];
            float4 o;
            o.x = acc[i][0] * inv;
            o.y = acc[i][1] * inv;
            o.z = acc[i][2] * inv;
            o.w = acc[i][3] * inv;
            *(float4*)(g_att + base + (size_t)t * DIMV + tx * 4) = o;
        }
    }
}

// ---------------------------------------------------------------------------
// Launch
// ---------------------------------------------------------------------------
extern "C" void kernel_launch(void* const* d_in, const int* in_sizes, int n_in,
                              void* d_out, int out_size)
{
    const float* x  = (const float*)d_in[0];
    const float* Wq = (const float*)d_in[1];
    const float* bq = (const float*)d_in[2];
    const float* Wk = (const float*)d_in[3];
    const float* bk = (const float*)d_in[4];
    const float* Wv = (const float*)d_in[5];
    const float* bv = (const float*)d_in[6];
    const float* Wo = (const float*)d_in[7];
    const float* bo = (const float*)d_in[8];
    float* out = (float*)d_out;

    const int stats_smem = 2 * CHUNK * HD * (int)sizeof(float);              // 64 KB
    const int cout_smem  = (2 * HD * SMS + CHUNK * HD + HD * HD +
                            CHUNK * SMS + HD + CHUNK) * (int)sizeof(float);  // ~181 KB
    cudaFuncSetAttribute(chunk_stats_kernel,
                         cudaFuncAttributeMaxDynamicSharedMemorySize, stats_smem);
    cudaFuncSetAttribute(chunk_out_kernel,
                         cudaFuncAttributeMaxDynamicSharedMemorySize, cout_smem);

    dim3 blk(256);
    qkv_gemm_kernel<<<dim3(NDIM / 128, M_ROWS / 128, 3), blk>>>(
        x, Wq, bq, Wk, bk, Wv, bv);
    chunk_stats_kernel<<<dim3(NCHUNK, BHEADS), blk, stats_smem>>>();
    prefix_kernel<<<BHEADS, 256>>>();
    chunk_out_kernel<<<dim3(NCHUNK, BHEADS), blk, cout_smem>>>();
    out_gemm_kernel<<<dim3(NDIM / 128, M_ROWS / 128), blk>>>(Wo, bo, out);
}

// round 4
// speedup vs baseline: 1.2511x; 1.2511x over previous
#include <cuda_runtime.h>
#include <cstdint>

// Problem constants
#define S_LEN  2048
#define DIMV   1024
#define NHEAD  16
#define HD     64
#define BATCH  2
#define M_ROWS (BATCH * S_LEN)     // 4096
#define KDIM   1024
#define NDIM   1024
#define BHEADS (BATCH * NHEAD)     // 32
#define CHUNK  128
#define NCHUNK (S_LEN / CHUNK)     // 16

// ---------------------------------------------------------------------------
// Scratch (static device globals: allocation-free per harness rules)
// ---------------------------------------------------------------------------
__device__ float g_q[M_ROWS * DIMV];
__device__ float g_k[M_ROWS * DIMV];
__device__ float g_v[M_ROWS * DIMV];
__device__ float g_att[M_ROWS * DIMV];
__device__ float g_ckv[BHEADS * NCHUNK * HD * HD];
__device__ float g_ck1[BHEADS * NCHUNK * HD];
__device__ float g_pkv[BHEADS * NCHUNK * HD * HD];
__device__ float g_pk1[BHEADS * NCHUNK * HD];

#define SMS 132  // padded shared stride for the fp32 attention kernels

// ===========================================================================
// 3xTF32 mma.sync GEMM  (sm_100-compatible; no tcgen05)
// C[m,n] = sum_k A[m,k] * W[n,k] + bias[n], optional exp epilogue.
// CTA tile 128x128, 4 warps (64x64 each), BK=16, double-buffered smem.
// Each operand split hi/lo tf32; acc += ah*bh + ah*bl + al*bh.
// ===========================================================================
#define BK      16
#define NSTAGE  (KDIM / BK)   // 64
#define AST     20            // padded row stride in 4B words (16 + 4)
#define MATW    (128 * AST)   // 2560 words per matrix per buffer
#define BUFW    (4 * MATW)    // AH, AL, BH, BL
#define GEMM_SMEM_BYTES (2 * BUFW * 4)  // 81920

__device__ __forceinline__ uint32_t f2tf32(float f) {
    uint32_t r;
    asm("cvt.rna.tf32.f32 %0, %1;" : "=r"(r) : "f"(f));
    return r;
}

__device__ __forceinline__ void mma_tf32(float* d, const uint32_t* a,
                                         uint32_t b0, uint32_t b1) {
    asm volatile(
        "mma.sync.aligned.m16n8k8.row.col.f32.tf32.tf32.f32 "
        "{%0,%1,%2,%3}, {%4,%5,%6,%7}, {%8,%9}, {%0,%1,%2,%3};"
        : "+f"(d[0]), "+f"(d[1]), "+f"(d[2]), "+f"(d[3])
        : "r"(a[0]), "r"(a[1]), "r"(a[2]), "r"(a[3]), "r"(b0), "r"(b1));
}

__device__ __forceinline__ void gemm_3xtf32(
    const float* __restrict__ A, const float* __restrict__ W,
    const float* __restrict__ bias, float* __restrict__ out, int doExp,
    int m0, int n0)
{
    extern __shared__ uint32_t sh[];
    const int tid  = threadIdx.x;
    const int lane = tid & 31, wid = tid >> 5;
    const int wm = wid >> 1, wn = wid & 1;       // 2x2 warp grid
    const int grp = lane >> 2, tig = lane & 3;   // mma fragment coords
    const int r32 = tid >> 2, q4 = tid & 3;      // load coords

    const float* Ag = A + (size_t)(m0 + r32) * KDIM + q4 * 4;
    const float* Wg = W + (size_t)(n0 + r32) * KDIM + q4 * 4;

    float acc[4][8][4];
#pragma unroll
    for (int mt = 0; mt < 4; mt++)
#pragma unroll
        for (int nt = 0; nt < 8; nt++)
#pragma unroll
            for (int e = 0; e < 4; e++) acc[mt][nt][e] = 0.f;

    float4 a_st[4], b_st[4];

    // prologue: load stage 0
#pragma unroll
    for (int i = 0; i < 4; i++) {
        a_st[i] = *(const float4*)(Ag + (size_t)(32 * i) * KDIM);
        b_st[i] = *(const float4*)(Wg + (size_t)(32 * i) * KDIM);
    }
    {
        const int bo = 0;
#pragma unroll
        for (int i = 0; i < 4; i++) {
            const int w = (r32 + 32 * i) * AST + q4 * 4;
            const float* av = (const float*)&a_st[i];
            const float* bv = (const float*)&b_st[i];
            uint32_t h[4], l[4];
#pragma unroll
            for (int j = 0; j < 4; j++) {
                h[j] = f2tf32(av[j]);
                l[j] = f2tf32(av[j] - __uint_as_float(h[j]));
            }
            *(uint4*)&sh[bo + w]        = make_uint4(h[0], h[1], h[2], h[3]);
            *(uint4*)&sh[bo + MATW + w] = make_uint4(l[0], l[1], l[2], l[3]);
#pragma unroll
            for (int j = 0; j < 4; j++) {
                h[j] = f2tf32(bv[j]);
                l[j] = f2tf32(bv[j] - __uint_as_float(h[j]));
            }
            *(uint4*)&sh[bo + 2 * MATW + w] = make_uint4(h[0], h[1], h[2], h[3]);
            *(uint4*)&sh[bo + 3 * MATW + w] = make_uint4(l[0], l[1], l[2], l[3]);
        }
    }
    __syncthreads();

    for (int s = 0; s < NSTAGE; s++) {
        const int nxt = s + 1;
        if (nxt < NSTAGE) {
            const int k0 = nxt * BK;
#pragma unroll
            for (int i = 0; i < 4; i++) {
                a_st[i] = *(const float4*)(Ag + (size_t)(32 * i) * KDIM + k0);
                b_st[i] = *(const float4*)(Wg + (size_t)(32 * i) * KDIM + k0);
            }
        }

        // compute on buffer s&1
        {
            const int bo = (s & 1) * BUFW;
#pragma unroll
            for (int kk = 0; kk < BK; kk += 8) {
                uint32_t ah[4][4], al[4][4];
                const int c = kk + tig;
#pragma unroll
                for (int mt = 0; mt < 4; mt++) {
                    const int r = wm * 64 + mt * 16 + grp;
                    ah[mt][0] = sh[bo + r * AST + c];
                    ah[mt][1] = sh[bo + (r + 8) * AST + c];
                    ah[mt][2] = sh[bo + r * AST + c + 4];
                    ah[mt][3] = sh[bo + (r + 8) * AST + c + 4];
                    al[mt][0] = sh[bo + MATW + r * AST + c];
                    al[mt][1] = sh[bo + MATW + (r + 8) * AST + c];
                    al[mt][2] = sh[bo + MATW + r * AST + c + 4];
                    al[mt][3] = sh[bo + MATW + (r + 8) * AST + c + 4];
                }
#pragma unroll
                for (int nt = 0; nt < 8; nt++) {
                    const int rn = wn * 64 + nt * 8 + grp;
                    const uint32_t bh0 = sh[bo + 2 * MATW + rn * AST + c];
                    const uint32_t bh1 = sh[bo + 2 * MATW + rn * AST + c + 4];
                    const uint32_t bl0 = sh[bo + 3 * MATW + rn * AST + c];
                    const uint32_t bl1 = sh[bo + 3 * MATW + rn * AST + c + 4];
#pragma unroll
                    for (int mt = 0; mt < 4; mt++) {
                        mma_tf32(acc[mt][nt], ah[mt], bh0, bh1);
                        mma_tf32(acc[mt][nt], ah[mt], bl0, bl1);
                        mma_tf32(acc[mt][nt], al[mt], bh0, bh1);
                    }
                }
            }
        }

        if (nxt < NSTAGE) {
            const int bo = (nxt & 1) * BUFW;
#pragma unroll
            for (int i = 0; i < 4; i++) {
                const int w = (r32 + 32 * i) * AST + q4 * 4;
                const float* av = (const float*)&a_st[i];
                const float* bv = (const float*)&b_st[i];
                uint32_t h[4], l[4];
#pragma unroll
                for (int j = 0; j < 4; j++) {
                    h[j] = f2tf32(av[j]);
                    l[j] = f2tf32(av[j] - __uint_as_float(h[j]));
                }
                *(uint4*)&sh[bo + w]        = make_uint4(h[0], h[1], h[2], h[3]);
                *(uint4*)&sh[bo + MATW + w] = make_uint4(l[0], l[1], l[2], l[3]);
#pragma unroll
                for (int j = 0; j < 4; j++) {
                    h[j] = f2tf32(bv[j]);
                    l[j] = f2tf32(bv[j] - __uint_as_float(h[j]));
                }
                *(uint4*)&sh[bo + 2 * MATW + w] = make_uint4(h[0], h[1], h[2], h[3]);
                *(uint4*)&sh[bo + 3 * MATW + w] = make_uint4(l[0], l[1], l[2], l[3]);
            }
        }
        __syncthreads();
    }

    // epilogue
#pragma unroll
    for (int mt = 0; mt < 4; mt++) {
        const int r = m0 + wm * 64 + mt * 16 + grp;
#pragma unroll
        for (int nt = 0; nt < 8; nt++) {
            const int cc = n0 + wn * 64 + nt * 8 + 2 * tig;
            const float bb0 = bias[cc], bb1 = bias[cc + 1];
            float v0 = acc[mt][nt][0] + bb0;
            float v1 = acc[mt][nt][1] + bb1;
            float v2 = acc[mt][nt][2] + bb0;
            float v3 = acc[mt][nt][3] + bb1;
            if (doExp) {
                v0 = expf(v0); v1 = expf(v1); v2 = expf(v2); v3 = expf(v3);
            }
            float2 p0; p0.x = v0; p0.y = v1;
            float2 p1; p1.x = v2; p1.y = v3;
            *(float2*)&out[(size_t)r * NDIM + cc]       = p0;
            *(float2*)&out[(size_t)(r + 8) * NDIM + cc] = p1;
        }
    }
}

__global__ void __launch_bounds__(128) qkv_mma_kernel(
    const float* __restrict__ x,
    const float* __restrict__ Wq, const float* __restrict__ bq,
    const float* __restrict__ Wk, const float* __restrict__ bk,
    const float* __restrict__ Wv, const float* __restrict__ bv)
{
    const int z = blockIdx.z;
    const float* W    = (z == 0) ? Wq : ((z == 1) ? Wk : Wv);
    const float* bias = (z == 0) ? bq : ((z == 1) ? bk : bv);
    float* out        = (z == 0) ? g_q : ((z == 1) ? g_k : g_v);
    gemm_3xtf32(x, W, bias, out, z < 2, blockIdx.y * 128, blockIdx.x * 128);
}

__global__ void __launch_bounds__(128) out_mma_kernel(
    const float* __restrict__ Wo, const float* __restrict__ bo,
    float* __restrict__ out)
{
    gemm_3xtf32(g_att, Wo, bo, out, 0, blockIdx.y * 128, blockIdx.x * 128);
}

// ---------------------------------------------------------------------------
// Chunk stats: per (head, chunk) compute sum_t k_t v_t^T (64x64) and sum_t k_t
// ---------------------------------------------------------------------------
__global__ void __launch_bounds__(256) chunk_stats_kernel()
{
    extern __shared__ __align__(16) float sm[];
    float* Ks = sm;
    float* Vs = sm + CHUNK * HD;
    const int bh = blockIdx.y, c = blockIdx.x;
    const int b = bh >> 4, h = bh & 15;
    const int tid = threadIdx.x;
    const size_t base = ((size_t)(b * S_LEN + c * CHUNK)) * DIMV + h * HD;

#pragma unroll
    for (int it = 0; it < 8; it++) {
        const int idx = tid + it * 256;
        const int t = idx >> 4, dv = idx & 15;
        *(float4*)&Ks[t * HD + dv * 4] =
            *(const float4*)(g_k + base + (size_t)t * DIMV + dv * 4);
        *(float4*)&Vs[t * HD + dv * 4] =
            *(const float4*)(g_v + base + (size_t)t * DIMV + dv * 4);
    }
    __syncthreads();

    const int tx = tid & 15, ty = tid >> 4;
    float acc[4][4];
#pragma unroll
    for (int i = 0; i < 4; i++)
#pragma unroll
        for (int j = 0; j < 4; j++) acc[i][j] = 0.f;

#pragma unroll 4
    for (int t = 0; t < CHUNK; t++) {
        float kf[4], vf[4];
        *(float4*)kf = *(const float4*)&Ks[t * HD + ty * 4];
        *(float4*)vf = *(const float4*)&Vs[t * HD + tx * 4];
#pragma unroll
        for (int i = 0; i < 4; i++)
#pragma unroll
            for (int j = 0; j < 4; j++)
                acc[i][j] = fmaf(kf[i], vf[j], acc[i][j]);
    }

    float* okv = g_ckv + ((size_t)bh * NCHUNK + c) * HD * HD;
#pragma unroll
    for (int i = 0; i < 4; i++)
        *(float4*)&okv[(ty * 4 + i) * HD + tx * 4] = *(float4*)acc[i];

    if (tid < HD) {
        float s = 0.f;
#pragma unroll 8
        for (int t = 0; t < CHUNK; t++) s += Ks[t * HD + tid];
        g_ck1[((size_t)bh * NCHUNK + c) * HD + tid] = s;
    }
}

// ---------------------------------------------------------------------------
// Exclusive prefix over the 16 chunk states per head
// ---------------------------------------------------------------------------
__global__ void __launch_bounds__(256) prefix_kernel()
{
    const int bh = blockIdx.x, tid = threadIdx.x;
    for (int e = tid; e < HD * HD; e += 256) {
        float run = 0.f;
#pragma unroll
        for (int c = 0; c < NCHUNK; c++) {
            const size_t off = ((size_t)bh * NCHUNK + c) * HD * HD + e;
            g_pkv[off] = run;
            run += g_ckv[off];
        }
    }
    if (tid < HD) {
        float run = 0.f;
#pragma unroll
        for (int c = 0; c < NCHUNK; c++) {
            const size_t off = ((size_t)bh * NCHUNK + c) * HD + tid;
            g_pk1[off] = run;
            run += g_ck1[off];
        }
    }
}

// ---------------------------------------------------------------------------
// Chunk output: out_t = (q_t @ KVprev + sum_{t'<=t} (q_t.k_t') v_t') / den_t
// ---------------------------------------------------------------------------
__global__ void __launch_bounds__(256) chunk_out_kernel()
{
    extern __shared__ __align__(16) float sm[];
    float* QsT  = sm;
    float* KsT  = QsT + HD * SMS;
    float* Vs   = KsT + HD * SMS;
    float* Sp   = Vs + CHUNK * HD;
    float* Am   = Sp + HD * HD;
    float* k1p  = Am + CHUNK * SMS;
    float* dens = k1p + HD;

    const int bh = blockIdx.y, c = blockIdx.x;
    const int b = bh >> 4, h = bh & 15;
    const int tid = threadIdx.x;
    const size_t base = ((size_t)(b * S_LEN + c * CHUNK)) * DIMV + h * HD;

#pragma unroll
    for (int it = 0; it < 8; it++) {
        const int idx = tid + it * 256;
        const int t = idx >> 4, dv = idx & 15;
        float4 q4 = *(const float4*)(g_q + base + (size_t)t * DIMV + dv * 4);
        float4 k4 = *(const float4*)(g_k + base + (size_t)t * DIMV + dv * 4);
        float4 v4 = *(const float4*)(g_v + base + (size_t)t * DIMV + dv * 4);
        QsT[(dv * 4 + 0) * SMS + t] = q4.x;
        QsT[(dv * 4 + 1) * SMS + t] = q4.y;
        QsT[(dv * 4 + 2) * SMS + t] = q4.z;
        QsT[(dv * 4 + 3) * SMS + t] = q4.w;
        KsT[(dv * 4 + 0) * SMS + t] = k4.x;
        KsT[(dv * 4 + 1) * SMS + t] = k4.y;
        KsT[(dv * 4 + 2) * SMS + t] = k4.z;
        KsT[(dv * 4 + 3) * SMS + t] = k4.w;
        *(float4*)&Vs[t * HD + dv * 4] = v4;
    }
    {
        const float* spg = g_pkv + ((size_t)bh * NCHUNK + c) * HD * HD;
#pragma unroll
        for (int it = 0; it < 4; it++) {
            const int idx = (tid + it * 256) * 4;
            *(float4*)&Sp[idx] = *(const float4*)&spg[idx];
        }
        if (tid < HD) k1p[tid] = g_pk1[((size_t)bh * NCHUNK + c) * HD + tid];
    }
    __syncthreads();

    const int tx = tid & 15, ty = tid >> 4;

    {
        float acc[8][8];
#pragma unroll
        for (int i = 0; i < 8; i++)
#pragma unroll
            for (int j = 0; j < 8; j++) acc[i][j] = 0.f;
#pragma unroll 4
        for (int kk = 0; kk < HD; kk++) {
            float qf[8], kf[8];
            *(float4*)(qf)     = *(const float4*)&QsT[kk * SMS + ty * 8];
            *(float4*)(qf + 4) = *(const float4*)&QsT[kk * SMS + ty * 8 + 4];
            *(float4*)(kf)     = *(const float4*)&KsT[kk * SMS + tx * 8];
            *(float4*)(kf + 4) = *(const float4*)&KsT[kk * SMS + tx * 8 + 4];
#pragma unroll
            for (int i = 0; i < 8; i++)
#pragma unroll
                for (int j = 0; j < 8; j++)
                    acc[i][j] = fmaf(qf[i], kf[j], acc[i][j]);
        }
#pragma unroll
        for (int i = 0; i < 8; i++) {
            const int t = ty * 8 + i;
            float o[8];
#pragma unroll
            for (int j = 0; j < 8; j++) {
                const int tp = tx * 8 + j;
                o[j] = (tp <= t) ? acc[i][j] : 0.f;
            }
            *(float4*)&Am[t * SMS + tx * 8]     = *(float4*)o;
            *(float4*)&Am[t * SMS + tx * 8 + 4] = *(float4*)(o + 4);
        }
    }
    __syncthreads();

    if (tid < CHUNK) {
        const int t = tid;
        float s = 0.f;
#pragma unroll 8
        for (int d = 0; d < HD; d++) s = fmaf(QsT[d * SMS + t], k1p[d], s);
        for (int tp = 0; tp <= t; tp++) s += Am[t * SMS + tp];
        dens[t] = s;
    }
    __syncthreads();

    {
        float acc[8][4];
#pragma unroll
        for (int i = 0; i < 8; i++)
#pragma unroll
            for (int j = 0; j < 4; j++) acc[i][j] = 0.f;
#pragma unroll 4
        for (int tp = 0; tp < CHUNK; tp++) {
            float vf[4];
            *(float4*)vf = *(const float4*)&Vs[tp * HD + tx * 4];
#pragma unroll
            for (int i = 0; i < 8; i++) {
                const float a = Am[(ty * 8 + i) * SMS + tp];
#pragma unroll
                for (int j = 0; j < 4; j++) acc[i][j] = fmaf(a, vf[j], acc[i][j]);
            }
        }
#pragma unroll 4
        for (int d1 = 0; d1 < HD; d1++) {
            float vf[4];
            *(float4*)vf = *(const float4*)&Sp[d1 * HD + tx * 4];
#pragma unroll
            for (int i = 0; i < 8; i++) {
                const float a = QsT[d1 * SMS + ty * 8 + i];
#pragma unroll
                for (int j = 0; j < 4; j++) acc[i][j] = fmaf(a, vf[j], acc[i][j]);
            }
        }
#pragma unroll
        for (int i = 0; i < 8; i++) {
            const int t = ty * 8 + i;
            const float inv = 1.0f / dens[t];
            float4 o;
            o.x = acc[i][0] * inv;
            o.y = acc[i][1] * inv;
            o.z = acc[i][2] * inv;
            o.w = acc[i][3] * inv;
            *(float4*)(g_att + base + (size_t)t * DIMV + tx * 4) = o;
        }
    }
}

// ---------------------------------------------------------------------------
// Launch
// ---------------------------------------------------------------------------
extern "C" void kernel_launch(void* const* d_in, const int* in_sizes, int n_in,
                              void* d_out, int out_size)
{
    const float* x  = (const float*)d_in[0];
    const float* Wq = (const float*)d_in[1];
    const float* bq = (const float*)d_in[2];
    const float* Wk = (const float*)d_in[3];
    const float* bk = (const float*)d_in[4];
    const float* Wv = (const float*)d_in[5];
    const float* bv = (const float*)d_in[6];
    const float* Wo = (const float*)d_in[7];
    const float* bo = (const float*)d_in[8];
    float* out = (float*)d_out;

    const int gemm_smem  = GEMM_SMEM_BYTES;                                  // 80 KB
    const int stats_smem = 2 * CHUNK * HD * (int)sizeof(float);              // 64 KB
    const int cout_smem  = (2 * HD * SMS + CHUNK * HD + HD * HD +
                            CHUNK * SMS + HD + CHUNK) * (int)sizeof(float);  // ~181 KB
    cudaFuncSetAttribute(qkv_mma_kernel,
                         cudaFuncAttributeMaxDynamicSharedMemorySize, gemm_smem);
    cudaFuncSetAttribute(out_mma_kernel,
                         cudaFuncAttributeMaxDynamicSharedMemorySize, gemm_smem);
    cudaFuncSetAttribute(chunk_stats_kernel,
                         cudaFuncAttributeMaxDynamicSharedMemorySize, stats_smem);
    cudaFuncSetAttribute(chunk_out_kernel,
                         cudaFuncAttributeMaxDynamicSharedMemorySize, cout_smem);

    qkv_mma_kernel<<<dim3(NDIM / 128, M_ROWS / 128, 3), 128, gemm_smem>>>(
        x, Wq, bq, Wk, bk, Wv, bv);
    chunk_stats_kernel<<<dim3(NCHUNK, BHEADS), 256, stats_smem>>>();
    prefix_kernel<<<BHEADS, 256>>>();
    chunk_out_kernel<<<dim3(NCHUNK, BHEADS), 256, cout_smem>>>();
    out_mma_kernel<<<dim3(NDIM / 128, M_ROWS / 128), 128, gemm_smem>>>(Wo, bo, out);
}